// round 8
// baseline (speedup 1.0000x reference)
#include <cuda_runtime.h>
#include <cooperative_groups.h>

namespace cg = cooperative_groups;

#define BS 8192
#define C 23
#define F 1024
#define CF (C * F)         /* 23552 */
#define CF4 (CF / 4)       /* 5888  */
#define NCHUNK 8
#define ROWS (BS / NCHUNK) /* 1024 rows per chunk */
#define TPC 32             /* 32-row tiles per chunk (1024/32) */
#define EPS 1e-5f

// Scratch (__device__ globals; no allocations allowed)
__device__ float g_s[CF];        // fused per-(c,f) scale: rsqrt(var1+eps)*gamma1*W1
__device__ float g_h[C * BS];    // h TRANSPOSED: [c][b]
__device__ float g_mean2[C];
__device__ float g_k2[C];        // rsqrt(var2+eps)*gamma2*W2

// ---------------------------------------------------------------------------
// k1: per-(c,f) sums of x and x^2, chunk-parallel, with the cross-chunk fold
// done IN-KERNEL via an 8-CTA cluster + DSMEM (replaces the k2 launch and the
// 3 MB g_partial round trip). grid (23, 8), cluster (1,8,1), block 256.
// Each CTA streams a 1024-row chunk into shared (sum, sumsq); after
// cluster.sync, CTA r folds float4-slice [r*32, r*32+32) across all 8 peers
// in fixed order (deterministic) and writes s = rsqrt(var+eps)*gamma1*W1.
// Uniform evict-normal loads: L2 keeps the stream tail for k3 to harvest.
// ---------------------------------------------------------------------------
__global__ void __cluster_dims__(1, 8, 1)
k1_colsums(const float* __restrict__ x,
           const float* __restrict__ gamma1,
           const float* __restrict__ W1) {
    __shared__ float4 sm_s[256];
    __shared__ float4 sm_q[256];

    int cf4 = blockIdx.x * 256 + threadIdx.x;   // 0..5887
    int chunk = blockIdx.y;                     // 0..7 == cluster rank
    const float4* xp = (const float4*)x;
    long base = (long)chunk * ROWS * CF4 + cf4;

    float4 s = make_float4(0.f, 0.f, 0.f, 0.f);
    float4 q = make_float4(0.f, 0.f, 0.f, 0.f);
#pragma unroll 8
    for (int r = 0; r < ROWS; r++) {
        float4 v = __ldg(&xp[base + (long)r * CF4]);
        s.x += v.x; s.y += v.y; s.z += v.z; s.w += v.w;
        q.x += v.x * v.x; q.y += v.y * v.y; q.z += v.z * v.z; q.w += v.w * v.w;
    }
    sm_s[threadIdx.x] = s;
    sm_q[threadIdx.x] = q;

    cg::cluster_group cluster = cg::this_cluster();
    cluster.sync();

    // DSMEM fold: 32 threads per CTA, each owns one cf4 of this CTA's slice.
    if (threadIdx.x < 32) {
        int local = chunk * 32 + threadIdx.x;   // smem index 0..255
        float4 S = make_float4(0.f, 0.f, 0.f, 0.f);
        float4 Q = make_float4(0.f, 0.f, 0.f, 0.f);
#pragma unroll
        for (int r = 0; r < NCHUNK; r++) {      // fixed order -> deterministic
            const float4* ps = cluster.map_shared_rank(sm_s, r);
            const float4* pq = cluster.map_shared_rank(sm_q, r);
            float4 a = ps[local], b = pq[local];
            S.x += a.x; S.y += a.y; S.z += a.z; S.w += a.w;
            Q.x += b.x; Q.y += b.y; Q.z += b.z; Q.w += b.w;
        }
        int cfo = blockIdx.x * 256 + local;     // output cf4 index
        float4 g = ((const float4*)gamma1)[cfo];
        float4 w = ((const float4*)W1)[cfo];
        float4 o;
        float m;
        m = S.x * (1.0f / BS); o.x = rsqrtf(Q.x * (1.0f / BS) - m * m + EPS) * g.x * w.x;
        m = S.y * (1.0f / BS); o.y = rsqrtf(Q.y * (1.0f / BS) - m * m + EPS) * g.y * w.y;
        m = S.z * (1.0f / BS); o.z = rsqrtf(Q.z * (1.0f / BS) - m * m + EPS) * g.z * w.z;
        m = S.w * (1.0f / BS); o.w = rsqrtf(Q.w * (1.0f / BS) - m * m + EPS) * g.w * w.w;
        ((float4*)g_s)[cfo] = o;
    }

    // keep smem alive until all peers finished reading it
    cluster.sync();
}

// ---------------------------------------------------------------------------
// k3: h[c][b] = dot(x[b,c,:], s[c,:]).  Block = one channel c + 32 batch rows.
// Batch-tile schedule reversed per 1024-row chunk to harvest k1's L2 residue:
// early blocks take the tail tiles of every chunk, walking toward cold rows.
// grid 23*256 = 5888, block 256.
// ---------------------------------------------------------------------------
__global__ void k3_dot(const float* __restrict__ x) {
    __shared__ float4 ss[256];
    int c = blockIdx.x % C;
    int l = blockIdx.x / C;                     // launch-order tile index 0..255
    int rank  = l >> 3;                         // 0..31 (0 = hottest)
    int chunk = l & 7;                          // 0..7
    int btile = chunk * TPC + (TPC - 1 - rank); // actual 32-row tile
    ss[threadIdx.x] = ((const float4*)g_s)[c * 256 + threadIdx.x];
    __syncthreads();

    int w = threadIdx.x >> 5, lane = threadIdx.x & 31;
    int b0 = btile * 32 + w * 4;

    float acc[4];
#pragma unroll
    for (int j = 0; j < 4; j++) {
        const float4* xp = (const float4*)x + ((long)(b0 + j) * C + c) * 256;
        float a = 0.f;
#pragma unroll
        for (int i = 0; i < 8; i++) {
            float4 v  = __ldcs(&xp[lane + 32 * i]);   // no further reuse
            float4 wv = ss[lane + 32 * i];
            a += v.x * wv.x; a += v.y * wv.y;
            a += v.z * wv.z; a += v.w * wv.w;
        }
        acc[j] = a;
    }
#pragma unroll
    for (int o = 16; o; o >>= 1) {
#pragma unroll
        for (int j = 0; j < 4; j++)
            acc[j] += __shfl_xor_sync(0xffffffffu, acc[j], o);
    }
    if (lane == 0) {
        *(float4*)(&g_h[c * BS + b0]) =
            make_float4(acc[0], acc[1], acc[2], acc[3]);
    }
}

// ---------------------------------------------------------------------------
// k4: BatchNorm1d(23) batch stats over h[c][:] (contiguous, coalesced).
// grid 23, block 1024. (R5-proven tail config.)
// ---------------------------------------------------------------------------
__global__ void k4_stats(const float* __restrict__ gamma2,
                         const float* __restrict__ W2) {
    __shared__ float sh_s[32], sh_q[32];
    int c = blockIdx.x;
    int t = threadIdx.x, lane = t & 31, w = t >> 5;

    const float4* hp = (const float4*)(&g_h[c * BS]);
    float s = 0.f, q = 0.f;
#pragma unroll
    for (int i = 0; i < 2; i++) {
        float4 v = hp[t + 1024 * i];
        s += v.x + v.y + v.z + v.w;
        q += v.x * v.x + v.y * v.y + v.z * v.z + v.w * v.w;
    }
#pragma unroll
    for (int o = 16; o; o >>= 1) {
        s += __shfl_xor_sync(0xffffffffu, s, o);
        q += __shfl_xor_sync(0xffffffffu, q, o);
    }
    if (lane == 0) { sh_s[w] = s; sh_q[w] = q; }
    __syncthreads();
    if (w == 0) {
        s = sh_s[lane]; q = sh_q[lane];
#pragma unroll
        for (int o = 16; o; o >>= 1) {
            s += __shfl_xor_sync(0xffffffffu, s, o);
            q += __shfl_xor_sync(0xffffffffu, q, o);
        }
        if (lane == 0) {
            float mean = s * (1.0f / BS);
            float var  = q * (1.0f / BS) - mean * mean;
            g_mean2[c] = mean;
            g_k2[c]    = rsqrtf(var + EPS) * gamma2[c] * W2[c];
        }
    }
}

// ---------------------------------------------------------------------------
// k5: out[b] = sum_c (h[c][b]-mean2[c])*k2[c] + (sum_c beta2*W2 + b2)
// grid 32, block 256. h[c][b] reads coalesced; h is L2-resident.
// ---------------------------------------------------------------------------
__global__ void k5_out(const float* __restrict__ beta2,
                       const float* __restrict__ W2,
                       const float* __restrict__ b2,
                       float* __restrict__ out) {
    int b = blockIdx.x * 256 + threadIdx.x;
    float off = b2[0];
#pragma unroll
    for (int c = 0; c < C; c++) off += beta2[c] * W2[c];
    float a = 0.f;
#pragma unroll
    for (int c = 0; c < C; c++)
        a += (g_h[c * BS + b] - g_mean2[c]) * g_k2[c];
    out[b] = a + off;
}

extern "C" void kernel_launch(void* const* d_in, const int* in_sizes, int n_in,
                              void* d_out, int out_size) {
    const float* x      = (const float*)d_in[0];
    const float* gamma1 = (const float*)d_in[1];
    /* beta1 = d_in[2], b1 = d_in[4]: algebraically cancelled by BatchNorm1d(23) */
    const float* W1     = (const float*)d_in[3];
    const float* gamma2 = (const float*)d_in[5];
    const float* beta2  = (const float*)d_in[6];
    const float* W2     = (const float*)d_in[7];
    const float* b2     = (const float*)d_in[8];
    float* out = (float*)d_out;

    k1_colsums<<<dim3(23, NCHUNK), 256>>>(x, gamma1, W1);
    k3_dot<<<C * (BS / 32), 256>>>(x);
    k4_stats<<<C, 1024>>>(gamma2, W2);
    k5_out<<<BS / 256, 256>>>(beta2, W2, b2, out);
}

// round 9
// speedup vs baseline: 1.2192x; 1.2192x over previous
#include <cuda_runtime.h>

#define BS 8192
#define C 23
#define F 1024
#define CF (C * F)         /* 23552 */
#define CF4 (CF / 4)       /* 5888  */
#define NCHUNK 16
#define ROWS (BS / NCHUNK) /* 512 rows per chunk */
#define TPC 16             /* 32-row tiles per chunk (512/32) */
#define EPS 1e-5f

// Scratch (__device__ globals; no allocations allowed)
__device__ float g_partial[(size_t)NCHUNK * 2 * CF]; // [chunk][{sum,sumsq}][CF] ~3 MB
__device__ float g_s[CF];        // fused per-(c,f) scale: rsqrt(var1+eps)*gamma1*W1
__device__ float g_h[C * BS];    // h TRANSPOSED: [c][b]
__device__ float g_mean2[C];
__device__ float g_k2[C];        // rsqrt(var2+eps)*gamma2*W2

// ---------------------------------------------------------------------------
// k1: per-(c,f) partial sums of x and x^2 over a 512-row batch chunk.
// grid (23, 16), block 256 — all 368 blocks chip-resident, finish together.
// Uniform evict-normal loads: L2 keeps the stream tail for k3 to harvest.
// ---------------------------------------------------------------------------
__global__ void k1_colsums(const float* __restrict__ x) {
    int cf4 = blockIdx.x * 256 + threadIdx.x;   // 0..5887
    int chunk = blockIdx.y;                     // 0..15
    const float4* xp = (const float4*)x;
    long base = (long)chunk * ROWS * CF4 + cf4;

    float4 s = make_float4(0.f, 0.f, 0.f, 0.f);
    float4 q = make_float4(0.f, 0.f, 0.f, 0.f);
#pragma unroll 8
    for (int r = 0; r < ROWS; r++) {
        float4 v = __ldg(&xp[base + (long)r * CF4]);
        s.x += v.x; s.y += v.y; s.z += v.z; s.w += v.w;
        q.x += v.x * v.x; q.y += v.y * v.y; q.z += v.z * v.z; q.w += v.w * v.w;
    }
    ((float4*)g_partial)[(long)chunk * 2 * CF4 + cf4] = s;
    ((float4*)g_partial)[(long)chunk * 2 * CF4 + CF4 + cf4] = q;
}

// ---------------------------------------------------------------------------
// k2: fold NCHUNK partials -> s[c,f] = rsqrt(var1+eps) * gamma1 * W1
// grid 92, block 256. PDL: sync before reading g_partial.
// ---------------------------------------------------------------------------
__global__ void k2_scale(const float* __restrict__ gamma1,
                         const float* __restrict__ W1) {
    int cf = blockIdx.x * 256 + threadIdx.x;
    float g = gamma1[cf];                 // independent of k1 — prefetch pre-sync
    float w = W1[cf];
    cudaGridDependencySynchronize();      // wait for k1's g_partial
    float s = 0.f, q = 0.f;
#pragma unroll
    for (int k = 0; k < NCHUNK; k++) {
        s += g_partial[(long)k * 2 * CF + cf];
        q += g_partial[(long)k * 2 * CF + CF + cf];
    }
    float mean = s * (1.0f / BS);
    float var  = q * (1.0f / BS) - mean * mean;
    g_s[cf] = rsqrtf(var + EPS) * g * w;
}

// ---------------------------------------------------------------------------
// k3: h[c][b] = dot(x[b,c,:], s[c,:]).  Block = one channel c + 32 batch rows.
// Batch-tile schedule reversed per chunk to harvest k1's L2 residue.
// PDL: sync before reading g_s (x reads don't depend on k2, but keeping them
// after the sync preserves the proven L2-harvest timing).
// grid 23*256 = 5888, block 256.
// ---------------------------------------------------------------------------
__global__ void k3_dot(const float* __restrict__ x) {
    __shared__ float4 ss[256];
    int c = blockIdx.x % C;
    int l = blockIdx.x / C;                     // launch-order tile index 0..255
    int rank  = l >> 4;                         // 0..15 (0 = hottest)
    int chunk = l & 15;                         // 0..15
    int btile = chunk * TPC + (TPC - 1 - rank); // actual 32-row tile
    int w = threadIdx.x >> 5, lane = threadIdx.x & 31;
    int b0 = btile * 32 + w * 4;

    cudaGridDependencySynchronize();            // wait for k2's g_s
    ss[threadIdx.x] = ((const float4*)g_s)[c * 256 + threadIdx.x];
    __syncthreads();

    float acc[4];
#pragma unroll
    for (int j = 0; j < 4; j++) {
        const float4* xp = (const float4*)x + ((long)(b0 + j) * C + c) * 256;
        float a = 0.f;
#pragma unroll
        for (int i = 0; i < 8; i++) {
            float4 v  = __ldcs(&xp[lane + 32 * i]);   // no further reuse
            float4 wv = ss[lane + 32 * i];
            a += v.x * wv.x; a += v.y * wv.y;
            a += v.z * wv.z; a += v.w * wv.w;
        }
        acc[j] = a;
    }
#pragma unroll
    for (int o = 16; o; o >>= 1) {
#pragma unroll
        for (int j = 0; j < 4; j++)
            acc[j] += __shfl_xor_sync(0xffffffffu, acc[j], o);
    }
    if (lane == 0) {
        *(float4*)(&g_h[c * BS + b0]) =
            make_float4(acc[0], acc[1], acc[2], acc[3]);
    }
}

// ---------------------------------------------------------------------------
// k4: BatchNorm1d(23) batch stats over h[c][:] (contiguous, coalesced).
// grid 23, block 1024. PDL: sync before reading g_h.
// ---------------------------------------------------------------------------
__global__ void k4_stats(const float* __restrict__ gamma2,
                         const float* __restrict__ W2) {
    __shared__ float sh_s[32], sh_q[32];
    int c = blockIdx.x;
    int t = threadIdx.x, lane = t & 31, w = t >> 5;

    cudaGridDependencySynchronize();            // wait for k3's g_h
    const float4* hp = (const float4*)(&g_h[c * BS]);
    float s = 0.f, q = 0.f;
#pragma unroll
    for (int i = 0; i < 2; i++) {
        float4 v = hp[t + 1024 * i];
        s += v.x + v.y + v.z + v.w;
        q += v.x * v.x + v.y * v.y + v.z * v.z + v.w * v.w;
    }
#pragma unroll
    for (int o = 16; o; o >>= 1) {
        s += __shfl_xor_sync(0xffffffffu, s, o);
        q += __shfl_xor_sync(0xffffffffu, q, o);
    }
    if (lane == 0) { sh_s[w] = s; sh_q[w] = q; }
    __syncthreads();
    if (w == 0) {
        s = sh_s[lane]; q = sh_q[lane];
#pragma unroll
        for (int o = 16; o; o >>= 1) {
            s += __shfl_xor_sync(0xffffffffu, s, o);
            q += __shfl_xor_sync(0xffffffffu, q, o);
        }
        if (lane == 0) {
            float mean = s * (1.0f / BS);
            float var  = q * (1.0f / BS) - mean * mean;
            g_mean2[c] = mean;
            g_k2[c]    = rsqrtf(var + EPS) * gamma2[c] * W2[c];
        }
    }
}

// ---------------------------------------------------------------------------
// k5: out[b] = sum_c (h[c][b]-mean2[c])*k2[c] + (sum_c beta2*W2 + b2)
// grid 32, block 256. PDL: the off-term uses only harness inputs -> computed
// pre-sync (true epilogue overlap); g_h/g_mean2/g_k2 read post-sync.
// ---------------------------------------------------------------------------
__global__ void k5_out(const float* __restrict__ beta2,
                       const float* __restrict__ W2,
                       const float* __restrict__ b2,
                       float* __restrict__ out) {
    int b = blockIdx.x * 256 + threadIdx.x;
    float off = b2[0];
#pragma unroll
    for (int c = 0; c < C; c++) off += beta2[c] * W2[c];

    cudaGridDependencySynchronize();            // wait for k4 (=> k3 done too)
    float a = 0.f;
#pragma unroll
    for (int c = 0; c < C; c++)
        a += (g_h[c * BS + b] - g_mean2[c]) * g_k2[c];
    out[b] = a + off;
}

// ---------------------------------------------------------------------------
// PDL launch helper: programmatic stream serialization lets the next grid
// launch while the previous one drains; device-side sync guards the data.
// ---------------------------------------------------------------------------
template <typename K, typename... Args>
static void launch_pdl(dim3 grid, dim3 block, K kernel, Args... args) {
    cudaLaunchConfig_t cfg = {};
    cudaLaunchAttribute attr[1];
    attr[0].id = cudaLaunchAttributeProgrammaticStreamSerialization;
    attr[0].val.programmaticStreamSerializationAllowed = 1;
    cfg.gridDim = grid;
    cfg.blockDim = block;
    cfg.dynamicSmemBytes = 0;
    cfg.stream = 0;
    cfg.attrs = attr;
    cfg.numAttrs = 1;
    cudaLaunchKernelEx(&cfg, kernel, args...);
}

extern "C" void kernel_launch(void* const* d_in, const int* in_sizes, int n_in,
                              void* d_out, int out_size) {
    const float* x      = (const float*)d_in[0];
    const float* gamma1 = (const float*)d_in[1];
    /* beta1 = d_in[2], b1 = d_in[4]: algebraically cancelled by BatchNorm1d(23) */
    const float* W1     = (const float*)d_in[3];
    const float* gamma2 = (const float*)d_in[5];
    const float* beta2  = (const float*)d_in[6];
    const float* W2     = (const float*)d_in[7];
    const float* b2     = (const float*)d_in[8];
    float* out = (float*)d_out;

    k1_colsums<<<dim3(23, NCHUNK), 256>>>(x);
    launch_pdl(dim3(CF / 256), dim3(256), k2_scale, gamma1, W1);
    launch_pdl(dim3(C * (BS / 32)), dim3(256), k3_dot, x);
    launch_pdl(dim3(C), dim3(1024), k4_stats, gamma2, W2);
    launch_pdl(dim3(BS / 256), dim3(256), k5_out, beta2, W2, b2, out);
}